// round 3
// baseline (speedup 1.0000x reference)
#include <cuda_runtime.h>

#define N_NODES 100000
#define N_EDGES 1600000
#define FDIM    128
#define KHOPS   3
#define CONCAT  512            // (K+1)*128

// ---------------- static scratch (allocation-free) ----------------
__device__ int    g_cnt[N_NODES];
__device__ int    g_row[N_NODES + 1];
__device__ int    g_cur[N_NODES];
__device__ int    g_bsum[256];                      // 196 used
__device__ int    g_csr_src[N_EDGES];
__device__ float  g_norm[N_NODES];
__device__ float4 g_feats[(size_t)N_NODES * 128];   // [N][512] floats (concat buffer)
__device__ float4 g_tmpA [(size_t)N_NODES * 32];    // [N][128] pre-scaled messages
__device__ float4 g_tmpB [(size_t)N_NODES * 32];

// ---------------- degree / norm ----------------
__global__ void k_zero_cnt() {
    int i = blockIdx.x * blockDim.x + threadIdx.x;
    if (i < N_NODES) g_cnt[i] = 0;
}

__global__ void k_hist(const int* __restrict__ dst) {
    int e = blockIdx.x * blockDim.x + threadIdx.x;
    if (e < N_EDGES) atomicAdd(&g_cnt[dst[e]], 1);
}

__global__ void k_norm() {
    int i = blockIdx.x * blockDim.x + threadIdx.x;
    if (i < N_NODES) {
        int d = g_cnt[i];
        if (d < 1) d = 1;
        g_norm[i] = rsqrtf((float)d);
    }
}

// ---------------- exclusive scan (3 kernels) ----------------
#define SCAN_T 512
#define SCAN_NB ((N_NODES + SCAN_T - 1) / SCAN_T)   // 196

__global__ void k_scan1() {
    __shared__ int sh[SCAN_T];
    int tid = threadIdx.x;
    int gi  = blockIdx.x * SCAN_T + tid;
    int v   = (gi < N_NODES) ? g_cnt[gi] : 0;
    sh[tid] = v;
    __syncthreads();
    for (int off = 1; off < SCAN_T; off <<= 1) {
        int t = (tid >= off) ? sh[tid - off] : 0;
        __syncthreads();
        sh[tid] += t;
        __syncthreads();
    }
    if (gi < N_NODES) g_row[gi] = sh[tid] - v;       // exclusive, per-block
    if (tid == SCAN_T - 1) g_bsum[blockIdx.x] = sh[tid];
}

__global__ void k_scan2() {
    int running = 0;
    for (int b = 0; b < SCAN_NB; b++) {
        int t = g_bsum[b];
        g_bsum[b] = running;
        running += t;
    }
    g_row[N_NODES] = running;                        // == E
}

__global__ void k_scan3() {
    int gi = blockIdx.x * SCAN_T + threadIdx.x;
    if (gi < N_NODES) {
        int v = g_row[gi] + g_bsum[blockIdx.x];
        g_row[gi] = v;
        g_cur[gi] = v;
    }
}

__global__ void k_fill(const int* __restrict__ src, const int* __restrict__ dst) {
    int e = blockIdx.x * blockDim.x + threadIdx.x;
    if (e < N_EDGES) {
        int d   = dst[e];
        int pos = atomicAdd(&g_cur[d], 1);
        g_csr_src[pos] = src[e];
    }
}

// ---------------- copy x into slot0 + build scaled messages ----------------
__global__ void k_copy0(const float4* __restrict__ x4) {
    int idx = blockIdx.x * blockDim.x + threadIdx.x;   // N*32 float4
    int node = idx >> 5;
    int c    = idx & 31;
    float4 v = x4[idx];
    float  nm = g_norm[node];
    g_feats[(size_t)node * 128 + c] = v;               // slot 0 = x
    float4 t;
    t.x = v.x * nm; t.y = v.y * nm; t.z = v.z * nm; t.w = v.w * nm;
    g_tmpA[(size_t)node * 32 + c] = t;
}

// ---------------- aggregation hop: one warp per node ----------------
// dir==0: read tmpA, write tmpB.  dir==1: read tmpB, write tmpA.
__global__ __launch_bounds__(256) void k_agg(int slot, int dir) {
    int warp = threadIdx.x >> 5;
    int lane = threadIdx.x & 31;
    int node = blockIdx.x * 8 + warp;                  // grid = 12500, exact

    const float4* __restrict__ tin  = dir ? g_tmpB : g_tmpA;
    float4*       __restrict__ tout = dir ? g_tmpA : g_tmpB;

    int beg = g_row[node];
    int end = g_row[node + 1];

    float4 acc = make_float4(0.f, 0.f, 0.f, 0.f);
    int e = beg;
    for (; e + 4 <= end; e += 4) {
        int s0 = __ldg(&g_csr_src[e + 0]);
        int s1 = __ldg(&g_csr_src[e + 1]);
        int s2 = __ldg(&g_csr_src[e + 2]);
        int s3 = __ldg(&g_csr_src[e + 3]);
        float4 v0 = tin[(size_t)s0 * 32 + lane];
        float4 v1 = tin[(size_t)s1 * 32 + lane];
        float4 v2 = tin[(size_t)s2 * 32 + lane];
        float4 v3 = tin[(size_t)s3 * 32 + lane];
        acc.x += (v0.x + v1.x) + (v2.x + v3.x);
        acc.y += (v0.y + v1.y) + (v2.y + v3.y);
        acc.z += (v0.z + v1.z) + (v2.z + v3.z);
        acc.w += (v0.w + v1.w) + (v2.w + v3.w);
    }
    for (; e < end; e++) {
        int s = __ldg(&g_csr_src[e]);
        float4 v = tin[(size_t)s * 32 + lane];
        acc.x += v.x; acc.y += v.y; acc.z += v.z; acc.w += v.w;
    }

    float nm = g_norm[node];
    float4 h;
    h.x = acc.x * nm; h.y = acc.y * nm; h.z = acc.z * nm; h.w = acc.w * nm;
    g_feats[(size_t)node * 128 + slot * 32 + lane] = h;
    float4 t;
    t.x = h.x * nm; t.y = h.y * nm; t.z = h.z * nm; t.w = h.w * nm;
    tout[(size_t)node * 32 + lane] = t;
}

// ---------------- SGEMM: C[M,128] = relu(feats[M,512] @ W + b) ----------------
// mode 1: write into feats slot0 + tmpA (pre-scaled)   [layer-1 epilogue]
// mode 2: write into out                                [layer-2 epilogue]
__global__ __launch_bounds__(256) void k_gemm(const float* __restrict__ W,
                                              const float* __restrict__ bias,
                                              float* __restrict__ out,
                                              int mode) {
    __shared__ float As[16][132];   // [k][m], padded
    __shared__ float Bs[16][128];   // [k][n]

    const float* __restrict__ A = (const float*)g_feats;
    int tid  = threadIdx.x;
    int tx   = tid & 15;            // col group (8 cols each)
    int ty   = tid >> 4;            // row group (8 rows each)
    int row0 = blockIdx.x * 128;

    float acc[8][8];
#pragma unroll
    for (int i = 0; i < 8; i++)
#pragma unroll
        for (int j = 0; j < 8; j++) acc[i][j] = 0.f;

    for (int kt = 0; kt < CONCAT; kt += 16) {
        // load A tile 128x16 (512 float4; 2 per thread), store transposed
#pragma unroll
        for (int jj = 0; jj < 2; jj++) {
            int li = tid + jj * 256;
            int r  = li >> 2;
            int k4 = li & 3;
            int grow = row0 + r;
            float4 v = make_float4(0.f, 0.f, 0.f, 0.f);
            if (grow < N_NODES)
                v = *(const float4*)&A[(size_t)grow * CONCAT + kt + k4 * 4];
            As[k4 * 4 + 0][r] = v.x;
            As[k4 * 4 + 1][r] = v.y;
            As[k4 * 4 + 2][r] = v.z;
            As[k4 * 4 + 3][r] = v.w;
        }
        // load B tile 16x128 (512 float4; 2 per thread)
#pragma unroll
        for (int jj = 0; jj < 2; jj++) {
            int li = tid + jj * 256;
            int k  = li >> 5;
            int n4 = li & 31;
            float4 v = *(const float4*)&W[(size_t)(kt + k) * 128 + n4 * 4];
            *(float4*)&Bs[k][n4 * 4] = v;
        }
        __syncthreads();

#pragma unroll
        for (int k = 0; k < 16; k++) {
            float ra[8], rb[8];
#pragma unroll
            for (int i = 0; i < 8; i++) ra[i] = As[k][ty * 8 + i];
#pragma unroll
            for (int j = 0; j < 8; j++) rb[j] = Bs[k][tx * 8 + j];
#pragma unroll
            for (int i = 0; i < 8; i++)
#pragma unroll
                for (int j = 0; j < 8; j++) acc[i][j] += ra[i] * rb[j];
        }
        __syncthreads();
    }

    float bb[8];
#pragma unroll
    for (int j = 0; j < 8; j++) bb[j] = bias[tx * 8 + j];

#pragma unroll
    for (int i = 0; i < 8; i++) {
        int grow = row0 + ty * 8 + i;
        if (grow >= N_NODES) continue;
        float nm = (mode == 1) ? g_norm[grow] : 0.f;
#pragma unroll
        for (int j = 0; j < 8; j++) {
            float c = acc[i][j] + bb[j];
            c = c > 0.f ? c : 0.f;
            int col = tx * 8 + j;
            if (mode == 1) {
                ((float*)g_feats)[(size_t)grow * CONCAT + col] = c;  // slot 0 = relu(h)
                ((float*)g_tmpA)[(size_t)grow * FDIM + col] = c * nm;
            } else {
                out[(size_t)grow * FDIM + col] = c;
            }
        }
    }
}

// ---------------- launch ----------------
extern "C" void kernel_launch(void* const* d_in, const int* in_sizes, int n_in,
                              void* d_out, int out_size) {
    const float* x  = (const float*)d_in[0];
    const int*   ei = (const int*)  d_in[1];
    const float* W1 = (const float*)d_in[2];
    const float* b1 = (const float*)d_in[3];
    const float* W2 = (const float*)d_in[4];
    const float* b2 = (const float*)d_in[5];
    float* out = (float*)d_out;

    const int* src = ei;
    const int* dst = ei + N_EDGES;

    const int TB = 256;
    const int gN = (N_NODES + TB - 1) / TB;
    const int gE = (N_EDGES + TB - 1) / TB;

    // --- CSR-by-dst build + norms ---
    k_zero_cnt<<<gN, TB>>>();
    k_hist<<<gE, TB>>>(dst);
    k_norm<<<gN, TB>>>();
    k_scan1<<<SCAN_NB, SCAN_T>>>();
    k_scan2<<<1, 1>>>();
    k_scan3<<<SCAN_NB, SCAN_T>>>();
    k_fill<<<gE, TB>>>(src, dst);

    const int gAgg  = N_NODES / 8;                      // 12500
    const int gCpy  = (N_NODES * 32) / TB;              // 12500
    const int gGemm = (N_NODES + 127) / 128;            // 782

    // --- layer 1 ---
    k_copy0<<<gCpy, TB>>>((const float4*)x);
    k_agg<<<gAgg, TB>>>(1, 0);
    k_agg<<<gAgg, TB>>>(2, 1);
    k_agg<<<gAgg, TB>>>(3, 0);
    k_gemm<<<gGemm, TB>>>(W1, b1, nullptr, 1);

    // --- layer 2 ---
    k_agg<<<gAgg, TB>>>(1, 0);
    k_agg<<<gAgg, TB>>>(2, 1);
    k_agg<<<gAgg, TB>>>(3, 0);
    k_gemm<<<gGemm, TB>>>(W2, b2, out, 2);
}

// round 5
// speedup vs baseline: 1.0970x; 1.0970x over previous
#include <cuda_runtime.h>
#include <cuda_fp16.h>
#include <cstdint>

#define N_NODES 100000
#define N_EDGES 1600000
#define FDIM    128
#define CONCAT  512            // (K+1)*128

// ---------------- static scratch (allocation-free) ----------------
__device__ int     g_cnt[N_NODES];
__device__ int     g_row[N_NODES + 1];
__device__ int     g_cur[N_NODES];
__device__ int     g_bsum[256];                      // 196 used
__device__ int     g_csr_src[N_EDGES];
__device__ float   g_norm[N_NODES];
__device__ float4  g_feats[(size_t)N_NODES * 128];   // [N][512] fp32 concat buffer
// fp16 message buffers: 128 halfs per node = 32 uint2 per node (256B row)
__device__ uint2   g_tmpA[(size_t)N_NODES * 32];
__device__ uint2   g_tmpB[(size_t)N_NODES * 32];

// pack 4 floats -> uint2 of 2x half2
__device__ __forceinline__ uint2 pack4(float a, float b, float c, float d) {
    __half2 lo = __floats2half2_rn(a, b);
    __half2 hi = __floats2half2_rn(c, d);
    uint2 r;
    r.x = *(uint32_t*)&lo;
    r.y = *(uint32_t*)&hi;
    return r;
}

// ---------------- degree / norm ----------------
__global__ void k_zero_cnt() {
    int i = blockIdx.x * blockDim.x + threadIdx.x;
    if (i < N_NODES) g_cnt[i] = 0;
}
__global__ void k_hist(const int* __restrict__ dst) {
    int e = blockIdx.x * blockDim.x + threadIdx.x;
    if (e < N_EDGES) atomicAdd(&g_cnt[dst[e]], 1);
}
__global__ void k_norm() {
    int i = blockIdx.x * blockDim.x + threadIdx.x;
    if (i < N_NODES) {
        int d = g_cnt[i];
        if (d < 1) d = 1;
        g_norm[i] = rsqrtf((float)d);
    }
}

// ---------------- exclusive scan (3 kernels) ----------------
#define SCAN_T 512
#define SCAN_NB ((N_NODES + SCAN_T - 1) / SCAN_T)   // 196

__global__ void k_scan1() {
    __shared__ int sh[SCAN_T];
    int tid = threadIdx.x;
    int gi  = blockIdx.x * SCAN_T + tid;
    int v   = (gi < N_NODES) ? g_cnt[gi] : 0;
    sh[tid] = v;
    __syncthreads();
    for (int off = 1; off < SCAN_T; off <<= 1) {
        int t = (tid >= off) ? sh[tid - off] : 0;
        __syncthreads();
        sh[tid] += t;
        __syncthreads();
    }
    if (gi < N_NODES) g_row[gi] = sh[tid] - v;       // exclusive, per-block
    if (tid == SCAN_T - 1) g_bsum[blockIdx.x] = sh[tid];
}

// parallel block-sum scan (replaces 1-thread serial loop)
__global__ void k_scan2() {
    __shared__ int sh[256];
    int t = threadIdx.x;
    int v = (t < SCAN_NB) ? g_bsum[t] : 0;
    sh[t] = v;
    __syncthreads();
    for (int off = 1; off < 256; off <<= 1) {
        int u = (t >= off) ? sh[t - off] : 0;
        __syncthreads();
        sh[t] += u;
        __syncthreads();
    }
    if (t < SCAN_NB) g_bsum[t] = sh[t] - v;          // exclusive block offsets
}

__global__ void k_scan3() {
    int gi = blockIdx.x * SCAN_T + threadIdx.x;
    if (gi < N_NODES) {
        int v = g_row[gi] + g_bsum[blockIdx.x];
        g_row[gi] = v;
        g_cur[gi] = v;
    }
    if (gi == 0) g_row[N_NODES] = N_EDGES;
}

__global__ void k_fill(const int* __restrict__ src, const int* __restrict__ dst) {
    int e = blockIdx.x * blockDim.x + threadIdx.x;
    if (e < N_EDGES) {
        int d   = dst[e];
        int pos = atomicAdd(&g_cur[d], 1);
        g_csr_src[pos] = src[e];
    }
}

// ---------------- copy x into slot0 + build scaled fp16 messages ----------------
__global__ void k_copy0(const float4* __restrict__ x4) {
    int idx = blockIdx.x * blockDim.x + threadIdx.x;   // N*32 float4
    int node = idx >> 5;
    int c    = idx & 31;
    float4 v = x4[idx];
    float  nm = g_norm[node];
    g_feats[(size_t)node * 128 + c] = v;               // slot 0 = x (fp32)
    g_tmpA[(size_t)node * 32 + c] = pack4(v.x * nm, v.y * nm, v.z * nm, v.w * nm);
}

// ---------------- aggregation hop: one warp per node, fp16 gather ----------------
// dir==0: read tmpA, write tmpB.  dir==1: read tmpB, write tmpA.
__global__ __launch_bounds__(256) void k_agg(int slot, int dir) {
    int warp = threadIdx.x >> 5;
    int lane = threadIdx.x & 31;
    int node = blockIdx.x * 8 + warp;                  // grid = 12500, exact

    const uint2* __restrict__ tin  = dir ? g_tmpB : g_tmpA;
    uint2*       __restrict__ tout = dir ? g_tmpA : g_tmpB;

    int beg = g_row[node];
    int end = g_row[node + 1];

    float4 acc = make_float4(0.f, 0.f, 0.f, 0.f);
    int e = beg;
    for (; e + 4 <= end; e += 4) {
        int s0 = __ldg(&g_csr_src[e + 0]);
        int s1 = __ldg(&g_csr_src[e + 1]);
        int s2 = __ldg(&g_csr_src[e + 2]);
        int s3 = __ldg(&g_csr_src[e + 3]);
        uint2 u0 = tin[(size_t)s0 * 32 + lane];
        uint2 u1 = tin[(size_t)s1 * 32 + lane];
        uint2 u2 = tin[(size_t)s2 * 32 + lane];
        uint2 u3 = tin[(size_t)s3 * 32 + lane];
        float2 a0 = __half22float2(*(__half2*)&u0.x), b0 = __half22float2(*(__half2*)&u0.y);
        float2 a1 = __half22float2(*(__half2*)&u1.x), b1 = __half22float2(*(__half2*)&u1.y);
        float2 a2 = __half22float2(*(__half2*)&u2.x), b2 = __half22float2(*(__half2*)&u2.y);
        float2 a3 = __half22float2(*(__half2*)&u3.x), b3 = __half22float2(*(__half2*)&u3.y);
        acc.x += (a0.x + a1.x) + (a2.x + a3.x);
        acc.y += (a0.y + a1.y) + (a2.y + a3.y);
        acc.z += (b0.x + b1.x) + (b2.x + b3.x);
        acc.w += (b0.y + b1.y) + (b2.y + b3.y);
    }
    for (; e < end; e++) {
        int s = __ldg(&g_csr_src[e]);
        uint2 u = tin[(size_t)s * 32 + lane];
        float2 a = __half22float2(*(__half2*)&u.x);
        float2 b = __half22float2(*(__half2*)&u.y);
        acc.x += a.x; acc.y += a.y; acc.z += b.x; acc.w += b.y;
    }

    float nm = g_norm[node];
    float4 h;
    h.x = acc.x * nm; h.y = acc.y * nm; h.z = acc.z * nm; h.w = acc.w * nm;
    g_feats[(size_t)node * 128 + slot * 32 + lane] = h;        // fp32 concat slot
    tout[(size_t)node * 32 + lane] = pack4(h.x * nm, h.y * nm, h.z * nm, h.w * nm);
}

// ---------------- SGEMM: C[M,128] = relu(feats[M,512] @ W + b) ----------------
// mode 1: write into feats slot0 + tmpA (pre-scaled fp16)   [layer-1 epilogue]
// mode 2: write into out                                     [layer-2 epilogue]
__global__ __launch_bounds__(256) void k_gemm(const float* __restrict__ W,
                                              const float* __restrict__ bias,
                                              float* __restrict__ out,
                                              int mode) {
    __shared__ float As[16][132];   // [k][m], padded
    __shared__ float Bs[16][128];   // [k][n]

    const float* __restrict__ A = (const float*)g_feats;
    int tid  = threadIdx.x;
    int tx   = tid & 15;            // col group (8 cols each)
    int ty   = tid >> 4;            // row group (8 rows each)
    int row0 = blockIdx.x * 128;

    float acc[8][8];
#pragma unroll
    for (int i = 0; i < 8; i++)
#pragma unroll
        for (int j = 0; j < 8; j++) acc[i][j] = 0.f;

    for (int kt = 0; kt < CONCAT; kt += 16) {
        // load A tile 128x16 (512 float4; 2 per thread), store transposed
#pragma unroll
        for (int jj = 0; jj < 2; jj++) {
            int li = tid + jj * 256;
            int r  = li >> 2;
            int k4 = li & 3;
            int grow = row0 + r;
            float4 v = make_float4(0.f, 0.f, 0.f, 0.f);
            if (grow < N_NODES)
                v = *(const float4*)&A[(size_t)grow * CONCAT + kt + k4 * 4];
            As[k4 * 4 + 0][r] = v.x;
            As[k4 * 4 + 1][r] = v.y;
            As[k4 * 4 + 2][r] = v.z;
            As[k4 * 4 + 3][r] = v.w;
        }
        // load B tile 16x128 (512 float4; 2 per thread)
#pragma unroll
        for (int jj = 0; jj < 2; jj++) {
            int li = tid + jj * 256;
            int k  = li >> 5;
            int n4 = li & 31;
            float4 v = *(const float4*)&W[(size_t)(kt + k) * 128 + n4 * 4];
            *(float4*)&Bs[k][n4 * 4] = v;
        }
        __syncthreads();

#pragma unroll
        for (int k = 0; k < 16; k++) {
            float ra[8], rb[8];
#pragma unroll
            for (int i = 0; i < 8; i++) ra[i] = As[k][ty * 8 + i];
#pragma unroll
            for (int j = 0; j < 8; j++) rb[j] = Bs[k][tx * 8 + j];
#pragma unroll
            for (int i = 0; i < 8; i++)
#pragma unroll
                for (int j = 0; j < 8; j++) acc[i][j] += ra[i] * rb[j];
        }
        __syncthreads();
    }

    float bb[8];
#pragma unroll
    for (int j = 0; j < 8; j++) bb[j] = bias[tx * 8 + j];

#pragma unroll
    for (int i = 0; i < 8; i++) {
        int grow = row0 + ty * 8 + i;
        if (grow >= N_NODES) continue;
        float nm = (mode == 1) ? g_norm[grow] : 0.f;
#pragma unroll
        for (int j = 0; j < 8; j += 2) {
            float c0 = acc[i][j]     + bb[j];
            float c1 = acc[i][j + 1] + bb[j + 1];
            c0 = c0 > 0.f ? c0 : 0.f;
            c1 = c1 > 0.f ? c1 : 0.f;
            int col = tx * 8 + j;
            if (mode == 1) {
                float* frow = (float*)g_feats + (size_t)grow * CONCAT;
                frow[col]     = c0;                        // slot 0 = relu(h)
                frow[col + 1] = c1;
                __half2 t = __floats2half2_rn(c0 * nm, c1 * nm);
                ((uint32_t*)g_tmpA)[(size_t)grow * 64 + (col >> 1)] = *(uint32_t*)&t;
            } else {
                out[(size_t)grow * FDIM + col]     = c0;
                out[(size_t)grow * FDIM + col + 1] = c1;
            }
        }
    }
}

// ---------------- launch ----------------
extern "C" void kernel_launch(void* const* d_in, const int* in_sizes, int n_in,
                              void* d_out, int out_size) {
    const float* x  = (const float*)d_in[0];
    const int*   ei = (const int*)  d_in[1];
    const float* W1 = (const float*)d_in[2];
    const float* b1 = (const float*)d_in[3];
    const float* W2 = (const float*)d_in[4];
    const float* b2 = (const float*)d_in[5];
    float* out = (float*)d_out;

    const int* src = ei;
    const int* dst = ei + N_EDGES;

    const int TB = 256;
    const int gN = (N_NODES + TB - 1) / TB;
    const int gE = (N_EDGES + TB - 1) / TB;

    // --- CSR-by-dst build + norms ---
    k_zero_cnt<<<gN, TB>>>();
    k_hist<<<gE, TB>>>(dst);
    k_norm<<<gN, TB>>>();
    k_scan1<<<SCAN_NB, SCAN_T>>>();
    k_scan2<<<1, 256>>>();
    k_scan3<<<SCAN_NB, SCAN_T>>>();
    k_fill<<<gE, TB>>>(src, dst);

    const int gAgg  = N_NODES / 8;                      // 12500
    const int gCpy  = (N_NODES * 32) / TB;              // 12500
    const int gGemm = (N_NODES + 127) / 128;            // 782

    // --- layer 1 ---
    k_copy0<<<gCpy, TB>>>((const float4*)x);
    k_agg<<<gAgg, TB>>>(1, 0);
    k_agg<<<gAgg, TB>>>(2, 1);
    k_agg<<<gAgg, TB>>>(3, 0);
    k_gemm<<<gGemm, TB>>>(W1, b1, nullptr, 1);

    // --- layer 2 ---
    k_agg<<<gAgg, TB>>>(1, 0);
    k_agg<<<gAgg, TB>>>(2, 1);
    k_agg<<<gAgg, TB>>>(3, 0);
    k_gemm<<<gGemm, TB>>>(W2, b2, out, 2);
}

// round 6
// speedup vs baseline: 1.4436x; 1.3160x over previous
#include <cuda_runtime.h>
#include <cuda_fp16.h>
#include <cstdint>

#define N_NODES 100000
#define N_EDGES 1600000
#define FDIM    128
#define CONCAT  512            // (K+1)*128

// ---------------- static scratch (allocation-free) ----------------
__device__ int     g_cnt[N_NODES];
__device__ int     g_row[N_NODES + 1];
__device__ int     g_cur[N_NODES];
__device__ int     g_bsum[256];                      // 196 used
__device__ int     g_csr_src[N_EDGES];
__device__ float   g_norm[N_NODES];
__device__ float4  g_feats[(size_t)N_NODES * 128];   // [N][512] fp32 concat buffer
// fp16 message buffers: 128 halfs per node = 32 uint2 per node (256B row)
__device__ uint2   g_tmpA[(size_t)N_NODES * 32];
__device__ uint2   g_tmpB[(size_t)N_NODES * 32];
// W transposed to [n][k], fp16 hi/lo split (2-term fp16 trick)
__device__ __half  g_Wh1[128 * 512];
__device__ __half  g_Wl1[128 * 512];
__device__ __half  g_Wh2[128 * 512];
__device__ __half  g_Wl2[128 * 512];

// pack 4 floats -> uint2 of 2x half2
__device__ __forceinline__ uint2 pack4(float a, float b, float c, float d) {
    __half2 lo = __floats2half2_rn(a, b);
    __half2 hi = __floats2half2_rn(c, d);
    uint2 r;
    r.x = *(uint32_t*)&lo;
    r.y = *(uint32_t*)&hi;
    return r;
}

__device__ __forceinline__ uint32_t s2u(const void* p) {
    uint32_t a;
    asm("{ .reg .u64 t; cvta.to.shared.u64 t, %1; cvt.u32.u64 %0, t; }" : "=r"(a) : "l"(p));
    return a;
}

__device__ __forceinline__ void ldsm4(uint32_t* r, uint32_t addr) {
    asm volatile("ldmatrix.sync.aligned.m8n8.x4.shared.b16 {%0,%1,%2,%3}, [%4];"
                 : "=r"(r[0]), "=r"(r[1]), "=r"(r[2]), "=r"(r[3]) : "r"(addr));
}

__device__ __forceinline__ void mma16816(float* c, const uint32_t* a, const uint32_t* b) {
    asm volatile(
        "mma.sync.aligned.m16n8k16.row.col.f32.f16.f16.f32 "
        "{%0,%1,%2,%3}, {%4,%5,%6,%7}, {%8,%9}, {%0,%1,%2,%3};"
        : "+f"(c[0]), "+f"(c[1]), "+f"(c[2]), "+f"(c[3])
        : "r"(a[0]), "r"(a[1]), "r"(a[2]), "r"(a[3]), "r"(b[0]), "r"(b[1]));
}

// ---------------- degree / norm ----------------
__global__ void k_zero_cnt() {
    int i = blockIdx.x * blockDim.x + threadIdx.x;
    if (i < N_NODES) g_cnt[i] = 0;
}
__global__ void k_hist(const int* __restrict__ dst) {
    int e = blockIdx.x * blockDim.x + threadIdx.x;
    if (e < N_EDGES) atomicAdd(&g_cnt[dst[e]], 1);
}
__global__ void k_norm() {
    int i = blockIdx.x * blockDim.x + threadIdx.x;
    if (i < N_NODES) {
        int d = g_cnt[i];
        if (d < 1) d = 1;
        g_norm[i] = rsqrtf((float)d);
    }
}

// ---------------- exclusive scan (3 kernels) ----------------
#define SCAN_T 512
#define SCAN_NB ((N_NODES + SCAN_T - 1) / SCAN_T)   // 196

__global__ void k_scan1() {
    __shared__ int sh[SCAN_T];
    int tid = threadIdx.x;
    int gi  = blockIdx.x * SCAN_T + tid;
    int v   = (gi < N_NODES) ? g_cnt[gi] : 0;
    sh[tid] = v;
    __syncthreads();
    for (int off = 1; off < SCAN_T; off <<= 1) {
        int t = (tid >= off) ? sh[tid - off] : 0;
        __syncthreads();
        sh[tid] += t;
        __syncthreads();
    }
    if (gi < N_NODES) g_row[gi] = sh[tid] - v;       // exclusive, per-block
    if (tid == SCAN_T - 1) g_bsum[blockIdx.x] = sh[tid];
}

__global__ void k_scan2() {
    __shared__ int sh[256];
    int t = threadIdx.x;
    int v = (t < SCAN_NB) ? g_bsum[t] : 0;
    sh[t] = v;
    __syncthreads();
    for (int off = 1; off < 256; off <<= 1) {
        int u = (t >= off) ? sh[t - off] : 0;
        __syncthreads();
        sh[t] += u;
        __syncthreads();
    }
    if (t < SCAN_NB) g_bsum[t] = sh[t] - v;          // exclusive block offsets
}

__global__ void k_scan3() {
    int gi = blockIdx.x * SCAN_T + threadIdx.x;
    if (gi < N_NODES) {
        int v = g_row[gi] + g_bsum[blockIdx.x];
        g_row[gi] = v;
        g_cur[gi] = v;
    }
    if (gi == 0) g_row[N_NODES] = N_EDGES;
}

__global__ void k_fill(const int* __restrict__ src, const int* __restrict__ dst) {
    int e = blockIdx.x * blockDim.x + threadIdx.x;
    if (e < N_EDGES) {
        int d   = dst[e];
        int pos = atomicAdd(&g_cur[d], 1);
        g_csr_src[pos] = src[e];
    }
}

// ---------------- W prep: transpose + fp16 hi/lo split ----------------
__global__ void k_prepW(const float* __restrict__ W1, const float* __restrict__ W2) {
    int idx = blockIdx.x * blockDim.x + threadIdx.x;   // 512*128
    if (idx >= 512 * 128) return;
    int k = idx >> 7;
    int n = idx & 127;
    float w1 = W1[idx];
    __half h1 = __float2half_rn(w1);
    g_Wh1[n * 512 + k] = h1;
    g_Wl1[n * 512 + k] = __float2half_rn(w1 - __half2float(h1));
    float w2 = W2[idx];
    __half h2 = __float2half_rn(w2);
    g_Wh2[n * 512 + k] = h2;
    g_Wl2[n * 512 + k] = __float2half_rn(w2 - __half2float(h2));
}

// ---------------- copy x into slot0 + build scaled fp16 messages ----------------
__global__ void k_copy0(const float4* __restrict__ x4) {
    int idx = blockIdx.x * blockDim.x + threadIdx.x;   // N*32 float4
    int node = idx >> 5;
    int c    = idx & 31;
    float4 v = x4[idx];
    float  nm = g_norm[node];
    g_feats[(size_t)node * 128 + c] = v;               // slot 0 = x (fp32)
    g_tmpA[(size_t)node * 32 + c] = pack4(v.x * nm, v.y * nm, v.z * nm, v.w * nm);
}

// ---------------- aggregation hop: one warp per node, fp16 gather ----------------
__global__ __launch_bounds__(256) void k_agg(int slot, int dir) {
    int warp = threadIdx.x >> 5;
    int lane = threadIdx.x & 31;
    int node = blockIdx.x * 8 + warp;                  // grid = 12500, exact

    const uint2* __restrict__ tin  = dir ? g_tmpB : g_tmpA;
    uint2*       __restrict__ tout = dir ? g_tmpA : g_tmpB;

    int beg = g_row[node];
    int end = g_row[node + 1];

    float4 acc = make_float4(0.f, 0.f, 0.f, 0.f);
    int e = beg;
    for (; e + 4 <= end; e += 4) {
        int s0 = __ldg(&g_csr_src[e + 0]);
        int s1 = __ldg(&g_csr_src[e + 1]);
        int s2 = __ldg(&g_csr_src[e + 2]);
        int s3 = __ldg(&g_csr_src[e + 3]);
        uint2 u0 = tin[(size_t)s0 * 32 + lane];
        uint2 u1 = tin[(size_t)s1 * 32 + lane];
        uint2 u2 = tin[(size_t)s2 * 32 + lane];
        uint2 u3 = tin[(size_t)s3 * 32 + lane];
        float2 a0 = __half22float2(*(__half2*)&u0.x), b0 = __half22float2(*(__half2*)&u0.y);
        float2 a1 = __half22float2(*(__half2*)&u1.x), b1 = __half22float2(*(__half2*)&u1.y);
        float2 a2 = __half22float2(*(__half2*)&u2.x), b2 = __half22float2(*(__half2*)&u2.y);
        float2 a3 = __half22float2(*(__half2*)&u3.x), b3 = __half22float2(*(__half2*)&u3.y);
        acc.x += (a0.x + a1.x) + (a2.x + a3.x);
        acc.y += (a0.y + a1.y) + (a2.y + a3.y);
        acc.z += (b0.x + b1.x) + (b2.x + b3.x);
        acc.w += (b0.y + b1.y) + (b2.y + b3.y);
    }
    for (; e < end; e++) {
        int s = __ldg(&g_csr_src[e]);
        uint2 u = tin[(size_t)s * 32 + lane];
        float2 a = __half22float2(*(__half2*)&u.x);
        float2 b = __half22float2(*(__half2*)&u.y);
        acc.x += a.x; acc.y += a.y; acc.z += b.x; acc.w += b.y;
    }

    float nm = g_norm[node];
    float4 h;
    h.x = acc.x * nm; h.y = acc.y * nm; h.z = acc.z * nm; h.w = acc.w * nm;
    g_feats[(size_t)node * 128 + slot * 32 + lane] = h;        // fp32 concat slot
    tout[(size_t)node * 32 + lane] = pack4(h.x * nm, h.y * nm, h.z * nm, h.w * nm);
}

// ---------------- HMMA GEMM: relu(feats[M,512] @ W + b), fp16x2-split ----------------
// Block tile 128x128, 256 threads = 4(M) x 2(N) warps, each warp 32x64.
// Smem rows padded to 80B -> conflict-free ldmatrix.
#define ASTRIDE 80
__global__ __launch_bounds__(256, 1) void k_gemm_mma(const __half* __restrict__ Wh,
                                                     const __half* __restrict__ Wl,
                                                     const float* __restrict__ bias,
                                                     float* __restrict__ out,
                                                     int mode) {
    __shared__ __align__(16) char sAh[128 * ASTRIDE];
    __shared__ __align__(16) char sAl[128 * ASTRIDE];
    __shared__ __align__(16) char sBh[128 * ASTRIDE];
    __shared__ __align__(16) char sBl[128 * ASTRIDE];
    __shared__ float sBias[128];

    int tid  = threadIdx.x;
    int lane = tid & 31;
    int wid  = tid >> 5;
    int wm   = wid & 3;          // 0..3 -> M offset wm*32
    int wn   = wid >> 2;         // 0..1 -> N offset wn*64
    int row0 = blockIdx.x * 128;

    if (tid < 128) sBias[tid] = bias[tid];

    const float* __restrict__ Af = (const float*)g_feats;
    uint32_t aAh = s2u(sAh), aAl = s2u(sAl), aBh = s2u(sBh), aBl = s2u(sBl);

    // ldmatrix address selectors
    uint32_t aRow = (lane & 7) + ((lane >> 3) & 1) * 8;   // A: m within tile
    uint32_t aCol = (lane >> 4) * 16;                     // A: k-byte within tile
    uint32_t bRow = (lane & 7) + (lane >> 4) * 8;         // B: n within tile-pair
    uint32_t bCol = ((lane >> 3) & 1) * 16;               // B: k-byte

    float acc[2][8][4];
#pragma unroll
    for (int mt = 0; mt < 2; mt++)
#pragma unroll
        for (int nt = 0; nt < 8; nt++)
#pragma unroll
            for (int q = 0; q < 4; q++) acc[mt][nt][q] = 0.f;

    for (int kc = 0; kc < 16; kc++) {
        // --- stage A: 128x32 fp32 -> split -> fp16 hi/lo smem ---
#pragma unroll
        for (int jj = 0; jj < 4; jj++) {
            int f  = jj * 256 + tid;        // float4 id, 1024 total
            int r  = f >> 3;
            int k4 = f & 7;
            int grow = row0 + r;
            if (grow > N_NODES - 1) grow = N_NODES - 1;
            float4 v = *(const float4*)(Af + (size_t)grow * CONCAT + kc * 32 + k4 * 4);
            __half2 h01 = __floats2half2_rn(v.x, v.y);
            __half2 h23 = __floats2half2_rn(v.z, v.w);
            float2 f01 = __half22float2(h01);
            float2 f23 = __half22float2(h23);
            __half2 l01 = __floats2half2_rn(v.x - f01.x, v.y - f01.y);
            __half2 l23 = __floats2half2_rn(v.z - f23.x, v.w - f23.y);
            uint2 hu; hu.x = *(uint32_t*)&h01; hu.y = *(uint32_t*)&h23;
            uint2 lu; lu.x = *(uint32_t*)&l01; lu.y = *(uint32_t*)&l23;
            *(uint2*)(sAh + r * ASTRIDE + k4 * 8) = hu;
            *(uint2*)(sAl + r * ASTRIDE + k4 * 8) = lu;
        }
        // --- stage B: Wt[n][k] fp16 hi/lo, 128x32 each ---
#pragma unroll
        for (int jj = 0; jj < 2; jj++) {
            int f = jj * 256 + tid;         // uint4 id, 512 total
            int r = f >> 2;
            int s = f & 3;
            size_t go = ((size_t)r * 512 + kc * 32) * 2 + s * 16;
            *(uint4*)(sBh + r * ASTRIDE + s * 16) = *(const uint4*)((const char*)Wh + go);
            *(uint4*)(sBl + r * ASTRIDE + s * 16) = *(const uint4*)((const char*)Wl + go);
        }
        __syncthreads();

#pragma unroll
        for (int ks = 0; ks < 2; ks++) {
            uint32_t kb = ks * 32;
            uint32_t ah[2][4], al[2][4];
#pragma unroll
            for (int mt = 0; mt < 2; mt++) {
                uint32_t row = wm * 32 + mt * 16 + aRow;
                ldsm4(ah[mt], aAh + row * ASTRIDE + kb + aCol);
                ldsm4(al[mt], aAl + row * ASTRIDE + kb + aCol);
            }
            uint32_t bh[4][4], bl[4][4];
#pragma unroll
            for (int np = 0; np < 4; np++) {
                uint32_t row = wn * 64 + np * 16 + bRow;
                ldsm4(bh[np], aBh + row * ASTRIDE + kb + bCol);
                ldsm4(bl[np], aBl + row * ASTRIDE + kb + bCol);
            }
#pragma unroll
            for (int mt = 0; mt < 2; mt++)
#pragma unroll
                for (int nt = 0; nt < 8; nt++) {
                    const uint32_t* fh = &bh[nt >> 1][(nt & 1) * 2];
                    const uint32_t* fl = &bl[nt >> 1][(nt & 1) * 2];
                    float* c = acc[mt][nt];
                    mma16816(c, ah[mt], fh);   // hi*hi
                    mma16816(c, al[mt], fh);   // lo*hi
                    mma16816(c, ah[mt], fl);   // hi*lo
                }
        }
        __syncthreads();
    }

    // --- epilogue: bias + relu + fused stores ---
    int qr = lane >> 2;
    int qc = lane & 3;
#pragma unroll
    for (int mt = 0; mt < 2; mt++) {
#pragma unroll
        for (int half = 0; half < 2; half++) {        // c0,c1 vs c2,c3
            int m = row0 + wm * 32 + mt * 16 + qr + half * 8;
            if (m >= N_NODES) continue;
            float nm = (mode == 1) ? g_norm[m] : 0.f;
            float* frow = (float*)g_feats + (size_t)m * CONCAT;
            float* orow = out + (size_t)m * FDIM;
            uint32_t* trow = (uint32_t*)g_tmpA + (size_t)m * 64;
#pragma unroll
            for (int nt = 0; nt < 8; nt++) {
                int col = wn * 64 + nt * 8 + qc * 2;
                float c0 = acc[mt][nt][half * 2 + 0] + sBias[col];
                float c1 = acc[mt][nt][half * 2 + 1] + sBias[col + 1];
                c0 = c0 > 0.f ? c0 : 0.f;
                c1 = c1 > 0.f ? c1 : 0.f;
                if (mode == 1) {
                    *(float2*)(frow + col) = make_float2(c0, c1);    // slot 0 = relu(h)
                    __half2 t = __floats2half2_rn(c0 * nm, c1 * nm);
                    trow[col >> 1] = *(uint32_t*)&t;                 // pre-scaled msg
                } else {
                    *(float2*)(orow + col) = make_float2(c0, c1);
                }
            }
        }
    }
}

// ---------------- launch ----------------
extern "C" void kernel_launch(void* const* d_in, const int* in_sizes, int n_in,
                              void* d_out, int out_size) {
    const float* x  = (const float*)d_in[0];
    const int*   ei = (const int*)  d_in[1];
    const float* W1 = (const float*)d_in[2];
    const float* b1 = (const float*)d_in[3];
    const float* W2 = (const float*)d_in[4];
    const float* b2 = (const float*)d_in[5];
    float* out = (float*)d_out;

    const int* src = ei;
    const int* dst = ei + N_EDGES;

    const int TB = 256;
    const int gN = (N_NODES + TB - 1) / TB;
    const int gE = (N_EDGES + TB - 1) / TB;

    // device-symbol addresses for the prepped weights
    __half *wh1, *wl1, *wh2, *wl2;
    cudaGetSymbolAddress((void**)&wh1, g_Wh1);
    cudaGetSymbolAddress((void**)&wl1, g_Wl1);
    cudaGetSymbolAddress((void**)&wh2, g_Wh2);
    cudaGetSymbolAddress((void**)&wl2, g_Wl2);

    // --- CSR-by-dst build + norms + W prep ---
    k_zero_cnt<<<gN, TB>>>();
    k_hist<<<gE, TB>>>(dst);
    k_norm<<<gN, TB>>>();
    k_scan1<<<SCAN_NB, SCAN_T>>>();
    k_scan2<<<1, 256>>>();
    k_scan3<<<SCAN_NB, SCAN_T>>>();
    k_fill<<<gE, TB>>>(src, dst);
    k_prepW<<<(512 * 128) / TB, TB>>>(W1, W2);

    const int gAgg  = N_NODES / 8;                      // 12500
    const int gCpy  = (N_NODES * 32) / TB;              // 12500
    const int gGemm = (N_NODES + 127) / 128;            // 782

    // --- layer 1 ---
    k_copy0<<<gCpy, TB>>>((const float4*)x);
    k_agg<<<gAgg, TB>>>(1, 0);
    k_agg<<<gAgg, TB>>>(2, 1);
    k_agg<<<gAgg, TB>>>(3, 0);
    k_gemm_mma<<<gGemm, TB>>>(wh1, wl1, b1, nullptr, 1);

    // --- layer 2 ---
    k_agg<<<gAgg, TB>>>(1, 0);
    k_agg<<<gAgg, TB>>>(2, 1);
    k_agg<<<gAgg, TB>>>(3, 0);
    k_gemm_mma<<<gGemm, TB>>>(wh2, wl2, b2, out, 2);
}

// round 7
// speedup vs baseline: 2.2027x; 1.5258x over previous
#include <cuda_runtime.h>
#include <cuda_fp16.h>
#include <cstdint>

#define N_NODES 100000
#define N_EDGES 1600000
#define FDIM    128
#define CONCAT  512            // (K+1)*128

// ---------------- static scratch (allocation-free) ----------------
__device__ int     g_cnt[N_NODES];
__device__ int     g_row[N_NODES + 1];
__device__ int     g_cur[N_NODES];
__device__ int     g_bsum[256];                      // 196 used
__device__ int     g_csr_src[N_EDGES];
__device__ float   g_norm[N_NODES];
// fp16 concat buffer: [N][512] halfs = 64 uint4 per node
__device__ uint4   g_feats4[(size_t)N_NODES * 64];
// fp16 message buffers: [N][128] halfs = 16 uint4 per node
__device__ uint4   g_tmpA4[(size_t)N_NODES * 16];
__device__ uint4   g_tmpB4[(size_t)N_NODES * 16];
// W transposed to [n][k], fp16 hi/lo split
__device__ __half  g_Wh1[128 * 512];
__device__ __half  g_Wl1[128 * 512];
__device__ __half  g_Wh2[128 * 512];
__device__ __half  g_Wl2[128 * 512];

__device__ __forceinline__ void add8(float* a, uint4 u) {
    float2 p0 = __half22float2(*(__half2*)&u.x);
    float2 p1 = __half22float2(*(__half2*)&u.y);
    float2 p2 = __half22float2(*(__half2*)&u.z);
    float2 p3 = __half22float2(*(__half2*)&u.w);
    a[0] += p0.x; a[1] += p0.y; a[2] += p1.x; a[3] += p1.y;
    a[4] += p2.x; a[5] += p2.y; a[6] += p3.x; a[7] += p3.y;
}
__device__ __forceinline__ uint4 pack8(const float* a, float s) {
    __half2 h0 = __floats2half2_rn(a[0] * s, a[1] * s);
    __half2 h1 = __floats2half2_rn(a[2] * s, a[3] * s);
    __half2 h2 = __floats2half2_rn(a[4] * s, a[5] * s);
    __half2 h3 = __floats2half2_rn(a[6] * s, a[7] * s);
    uint4 u;
    u.x = *(uint32_t*)&h0; u.y = *(uint32_t*)&h1;
    u.z = *(uint32_t*)&h2; u.w = *(uint32_t*)&h3;
    return u;
}
__device__ __forceinline__ uint32_t s2u(const void* p) {
    uint32_t a;
    asm("{ .reg .u64 t; cvta.to.shared.u64 t, %1; cvt.u32.u64 %0, t; }" : "=r"(a) : "l"(p));
    return a;
}
__device__ __forceinline__ void ldsm4(uint32_t* r, uint32_t addr) {
    asm volatile("ldmatrix.sync.aligned.m8n8.x4.shared.b16 {%0,%1,%2,%3}, [%4];"
                 : "=r"(r[0]), "=r"(r[1]), "=r"(r[2]), "=r"(r[3]) : "r"(addr));
}
__device__ __forceinline__ void mma16816(float* c, const uint32_t* a, const uint32_t* b) {
    asm volatile(
        "mma.sync.aligned.m16n8k16.row.col.f32.f16.f16.f32 "
        "{%0,%1,%2,%3}, {%4,%5,%6,%7}, {%8,%9}, {%0,%1,%2,%3};"
        : "+f"(c[0]), "+f"(c[1]), "+f"(c[2]), "+f"(c[3])
        : "r"(a[0]), "r"(a[1]), "r"(a[2]), "r"(a[3]), "r"(b[0]), "r"(b[1]));
}

// ---------------- degree / norm ----------------
__global__ void k_zero_cnt() {
    int i = blockIdx.x * blockDim.x + threadIdx.x;
    if (i < N_NODES) g_cnt[i] = 0;
}
__global__ void k_hist(const int* __restrict__ dst) {
    int e = blockIdx.x * blockDim.x + threadIdx.x;
    if (e < N_EDGES) atomicAdd(&g_cnt[dst[e]], 1);
}
__global__ void k_norm() {
    int i = blockIdx.x * blockDim.x + threadIdx.x;
    if (i < N_NODES) {
        int d = g_cnt[i];
        if (d < 1) d = 1;
        g_norm[i] = rsqrtf((float)d);
    }
}

// ---------------- exclusive scan ----------------
#define SCAN_T 512
#define SCAN_NB ((N_NODES + SCAN_T - 1) / SCAN_T)   // 196

__global__ void k_scan1() {
    __shared__ int sh[SCAN_T];
    int tid = threadIdx.x;
    int gi  = blockIdx.x * SCAN_T + tid;
    int v   = (gi < N_NODES) ? g_cnt[gi] : 0;
    sh[tid] = v;
    __syncthreads();
    for (int off = 1; off < SCAN_T; off <<= 1) {
        int t = (tid >= off) ? sh[tid - off] : 0;
        __syncthreads();
        sh[tid] += t;
        __syncthreads();
    }
    if (gi < N_NODES) g_row[gi] = sh[tid] - v;
    if (tid == SCAN_T - 1) g_bsum[blockIdx.x] = sh[tid];
}
__global__ void k_scan2() {
    __shared__ int sh[256];
    int t = threadIdx.x;
    int v = (t < SCAN_NB) ? g_bsum[t] : 0;
    sh[t] = v;
    __syncthreads();
    for (int off = 1; off < 256; off <<= 1) {
        int u = (t >= off) ? sh[t - off] : 0;
        __syncthreads();
        sh[t] += u;
        __syncthreads();
    }
    if (t < SCAN_NB) g_bsum[t] = sh[t] - v;
}
__global__ void k_scan3() {
    int gi = blockIdx.x * SCAN_T + threadIdx.x;
    if (gi < N_NODES) {
        int v = g_row[gi] + g_bsum[blockIdx.x];
        g_row[gi] = v;
        g_cur[gi] = v;
    }
    if (gi == 0) g_row[N_NODES] = N_EDGES;
}
__global__ void k_fill(const int* __restrict__ src, const int* __restrict__ dst) {
    int e = blockIdx.x * blockDim.x + threadIdx.x;
    if (e < N_EDGES) {
        int d   = dst[e];
        int pos = atomicAdd(&g_cur[d], 1);
        g_csr_src[pos] = src[e];
    }
}

// ---------------- W prep: transpose + fp16 hi/lo split ----------------
__global__ void k_prepW(const float* __restrict__ W1, const float* __restrict__ W2) {
    int idx = blockIdx.x * blockDim.x + threadIdx.x;   // 512*128
    if (idx >= 512 * 128) return;
    int k = idx >> 7;
    int n = idx & 127;
    float w1 = W1[idx];
    __half h1 = __float2half_rn(w1);
    g_Wh1[n * 512 + k] = h1;
    g_Wl1[n * 512 + k] = __float2half_rn(w1 - __half2float(h1));
    float w2 = W2[idx];
    __half h2 = __float2half_rn(w2);
    g_Wh2[n * 512 + k] = h2;
    g_Wl2[n * 512 + k] = __float2half_rn(w2 - __half2float(h2));
}

// ---------------- copy x into slot0 (fp16) + scaled fp16 messages ----------------
__global__ void k_copy0(const float4* __restrict__ x4) {
    int idx = blockIdx.x * blockDim.x + threadIdx.x;   // N*16
    int node = idx >> 4;
    int q    = idx & 15;
    float4 v0 = x4[node * 32 + q * 2];
    float4 v1 = x4[node * 32 + q * 2 + 1];
    float a[8] = {v0.x, v0.y, v0.z, v0.w, v1.x, v1.y, v1.z, v1.w};
    float nm = g_norm[node];
    g_feats4[(size_t)node * 64 + q] = pack8(a, 1.f);     // slot 0 = x (fp16)
    g_tmpA4 [(size_t)node * 16 + q] = pack8(a, nm);
}

// ---------------- aggregation: half-warp per node, uint4 gathers ----------------
__global__ __launch_bounds__(256) void k_agg(int slot, int dir) {
    int hw   = threadIdx.x >> 4;                       // 0..15
    int hl   = threadIdx.x & 15;
    int node = blockIdx.x * 16 + hw;                   // grid = 6250, exact

    const uint4* __restrict__ tin  = dir ? g_tmpB4 : g_tmpA4;
    uint4*       __restrict__ tout = dir ? g_tmpA4 : g_tmpB4;

    int beg = g_row[node];
    int end = g_row[node + 1];

    float acc[8] = {0.f, 0.f, 0.f, 0.f, 0.f, 0.f, 0.f, 0.f};
    int e = beg;
    for (; e + 4 <= end; e += 4) {
        int s0 = __ldg(&g_csr_src[e + 0]);
        int s1 = __ldg(&g_csr_src[e + 1]);
        int s2 = __ldg(&g_csr_src[e + 2]);
        int s3 = __ldg(&g_csr_src[e + 3]);
        uint4 u0 = tin[(size_t)s0 * 16 + hl];
        uint4 u1 = tin[(size_t)s1 * 16 + hl];
        uint4 u2 = tin[(size_t)s2 * 16 + hl];
        uint4 u3 = tin[(size_t)s3 * 16 + hl];
        add8(acc, u0); add8(acc, u1); add8(acc, u2); add8(acc, u3);
    }
    for (; e < end; e++) {
        int s = __ldg(&g_csr_src[e]);
        add8(acc, tin[(size_t)s * 16 + hl]);
    }

    float nm = g_norm[node];
    g_feats4[(size_t)node * 64 + slot * 16 + hl] = pack8(acc, nm);       // h
    tout    [(size_t)node * 16 + hl]             = pack8(acc, nm * nm);  // h*nm
}

// ---------------- HMMA GEMM: relu(feats[M,512] @ W + b), A fp16, W hi/lo ----------------
// Block tile 128x128, 256 threads = 4(M) x 2(N) warps, each warp 32x64.
#define ASTRIDE 80
__global__ __launch_bounds__(256, 1) void k_gemm_mma(const __half* __restrict__ Wh,
                                                     const __half* __restrict__ Wl,
                                                     const float* __restrict__ bias,
                                                     float* __restrict__ out,
                                                     int mode) {
    __shared__ __align__(16) char sA [128 * ASTRIDE];
    __shared__ __align__(16) char sBh[128 * ASTRIDE];
    __shared__ __align__(16) char sBl[128 * ASTRIDE];
    __shared__ float sBias[128];

    int tid  = threadIdx.x;
    int lane = tid & 31;
    int wid  = tid >> 5;
    int wm   = wid & 3;          // M offset wm*32
    int wn   = wid >> 2;         // N offset wn*64
    int row0 = blockIdx.x * 128;

    if (tid < 128) sBias[tid] = bias[tid];

    const __half* __restrict__ Af = (const __half*)g_feats4;
    uint32_t aA = s2u(sA), aBh = s2u(sBh), aBl = s2u(sBl);

    uint32_t aRow = (lane & 7) + ((lane >> 3) & 1) * 8;
    uint32_t aCol = (lane >> 4) * 16;
    uint32_t bRow = (lane & 7) + (lane >> 4) * 8;
    uint32_t bCol = ((lane >> 3) & 1) * 16;

    float acc[2][8][4];
#pragma unroll
    for (int mt = 0; mt < 2; mt++)
#pragma unroll
        for (int nt = 0; nt < 8; nt++)
#pragma unroll
            for (int q = 0; q < 4; q++) acc[mt][nt][q] = 0.f;

    for (int kc = 0; kc < 16; kc++) {
        // --- stage A: 128 rows x 32 halfs, direct uint4 copies ---
#pragma unroll
        for (int jj = 0; jj < 2; jj++) {
            int f = jj * 256 + tid;          // 512 uint4
            int r = f >> 2;
            int q = f & 3;
            int grow = row0 + r;
            if (grow > N_NODES - 1) grow = N_NODES - 1;
            uint4 v = *((const uint4*)(Af + (size_t)grow * CONCAT + kc * 32) + q);
            *(uint4*)(sA + r * ASTRIDE + q * 16) = v;
        }
        // --- stage B: Wt[n][k] fp16 hi/lo ---
#pragma unroll
        for (int jj = 0; jj < 2; jj++) {
            int f = jj * 256 + tid;
            int r = f >> 2;
            int s = f & 3;
            size_t go = ((size_t)r * 512 + kc * 32) * 2 + s * 16;
            *(uint4*)(sBh + r * ASTRIDE + s * 16) = *(const uint4*)((const char*)Wh + go);
            *(uint4*)(sBl + r * ASTRIDE + s * 16) = *(const uint4*)((const char*)Wl + go);
        }
        __syncthreads();

#pragma unroll
        for (int ks = 0; ks < 2; ks++) {
            uint32_t kb = ks * 32;
            uint32_t ah[2][4];
#pragma unroll
            for (int mt = 0; mt < 2; mt++) {
                uint32_t row = wm * 32 + mt * 16 + aRow;
                ldsm4(ah[mt], aA + row * ASTRIDE + kb + aCol);
            }
            uint32_t bh[4][4], bl[4][4];
#pragma unroll
            for (int np = 0; np < 4; np++) {
                uint32_t row = wn * 64 + np * 16 + bRow;
                ldsm4(bh[np], aBh + row * ASTRIDE + kb + bCol);
                ldsm4(bl[np], aBl + row * ASTRIDE + kb + bCol);
            }
#pragma unroll
            for (int mt = 0; mt < 2; mt++)
#pragma unroll
                for (int nt = 0; nt < 8; nt++) {
                    const uint32_t* fh = &bh[nt >> 1][(nt & 1) * 2];
                    const uint32_t* fl = &bl[nt >> 1][(nt & 1) * 2];
                    float* c = acc[mt][nt];
                    mma16816(c, ah[mt], fh);   // A*Whi
                    mma16816(c, ah[mt], fl);   // A*Wlo
                }
        }
        __syncthreads();
    }

    // --- epilogue: bias + relu + fused stores ---
    int qr = lane >> 2;
    int qc = lane & 3;
#pragma unroll
    for (int mt = 0; mt < 2; mt++) {
#pragma unroll
        for (int half = 0; half < 2; half++) {
            int m = row0 + wm * 32 + mt * 16 + qr + half * 8;
            if (m >= N_NODES) continue;
            float nm = (mode == 1) ? g_norm[m] : 0.f;
            uint32_t* frow = (uint32_t*)g_feats4 + (size_t)m * 256;   // 512 halfs
            uint32_t* trow = (uint32_t*)g_tmpA4  + (size_t)m * 64;    // 128 halfs
            float*    orow = out + (size_t)m * FDIM;
#pragma unroll
            for (int nt = 0; nt < 8; nt++) {
                int col = wn * 64 + nt * 8 + qc * 2;
                float c0 = acc[mt][nt][half * 2 + 0] + sBias[col];
                float c1 = acc[mt][nt][half * 2 + 1] + sBias[col + 1];
                c0 = c0 > 0.f ? c0 : 0.f;
                c1 = c1 > 0.f ? c1 : 0.f;
                if (mode == 1) {
                    __half2 fh = __floats2half2_rn(c0, c1);
                    frow[col >> 1] = *(uint32_t*)&fh;                 // slot 0 = relu(h)
                    __half2 t = __floats2half2_rn(c0 * nm, c1 * nm);
                    trow[col >> 1] = *(uint32_t*)&t;                  // pre-scaled msg
                } else {
                    *(float2*)(orow + col) = make_float2(c0, c1);
                }
            }
        }
    }
}

// ---------------- launch ----------------
extern "C" void kernel_launch(void* const* d_in, const int* in_sizes, int n_in,
                              void* d_out, int out_size) {
    const float* x  = (const float*)d_in[0];
    const int*   ei = (const int*)  d_in[1];
    const float* W1 = (const float*)d_in[2];
    const float* b1 = (const float*)d_in[3];
    const float* W2 = (const float*)d_in[4];
    const float* b2 = (const float*)d_in[5];
    float* out = (float*)d_out;

    const int* src = ei;
    const int* dst = ei + N_EDGES;

    const int TB = 256;
    const int gN = (N_NODES + TB - 1) / TB;
    const int gE = (N_EDGES + TB - 1) / TB;

    __half *wh1, *wl1, *wh2, *wl2;
    cudaGetSymbolAddress((void**)&wh1, g_Wh1);
    cudaGetSymbolAddress((void**)&wl1, g_Wl1);
    cudaGetSymbolAddress((void**)&wh2, g_Wh2);
    cudaGetSymbolAddress((void**)&wl2, g_Wl2);

    // --- CSR-by-dst build + norms + W prep ---
    k_zero_cnt<<<gN, TB>>>();
    k_hist<<<gE, TB>>>(dst);
    k_norm<<<gN, TB>>>();
    k_scan1<<<SCAN_NB, SCAN_T>>>();
    k_scan2<<<1, 256>>>();
    k_scan3<<<SCAN_NB, SCAN_T>>>();
    k_fill<<<gE, TB>>>(src, dst);
    k_prepW<<<(512 * 128) / TB, TB>>>(W1, W2);

    const int gAgg  = N_NODES / 16;                     // 6250
    const int gCpy  = (N_NODES * 16) / TB;              // 6250
    const int gGemm = (N_NODES + 127) / 128;            // 782

    // --- layer 1 ---
    k_copy0<<<gCpy, TB>>>((const float4*)x);
    k_agg<<<gAgg, TB>>>(1, 0);
    k_agg<<<gAgg, TB>>>(2, 1);
    k_agg<<<gAgg, TB>>>(3, 0);
    k_gemm_mma<<<gGemm, TB>>>(wh1, wl1, b1, nullptr, 1);

    // --- layer 2 ---
    k_agg<<<gAgg, TB>>>(1, 0);
    k_agg<<<gAgg, TB>>>(2, 1);
    k_agg<<<gAgg, TB>>>(3, 0);
    k_gemm_mma<<<gGemm, TB>>>(wh2, wl2, b2, out, 2);
}

// round 8
// speedup vs baseline: 2.2384x; 1.0162x over previous
#include <cuda_runtime.h>
#include <cuda_fp16.h>
#include <cstdint>

#define N_NODES 100000
#define N_EDGES 1600000
#define FDIM    128
#define CONCAT  512            // (K+1)*128

// ---------------- static scratch (allocation-free) ----------------
__device__ int     g_cnt[N_NODES];
__device__ int     g_row[N_NODES + 1];
__device__ int     g_cur[N_NODES];
__device__ int     g_bsum[256];                      // 196 used
__device__ int     g_csr_src[N_EDGES];
__device__ float   g_norm[N_NODES];
// fp16 message buffers, one per hop slot: [N][128] halfs = 16 uint4 per node
// invariant: msg_s[m] = feats_s[m] * nm[m]  (so feats = msg / nm, row-uniform)
__device__ uint4   g_msg0[(size_t)N_NODES * 16];
__device__ uint4   g_msg1[(size_t)N_NODES * 16];
__device__ uint4   g_msg2[(size_t)N_NODES * 16];
__device__ uint4   g_msg3[(size_t)N_NODES * 16];
// W transposed to [n][k], fp16 hi/lo split
__device__ __half  g_Wh1[128 * 512];
__device__ __half  g_Wl1[128 * 512];
__device__ __half  g_Wh2[128 * 512];
__device__ __half  g_Wl2[128 * 512];

__device__ __forceinline__ void add8(float* a, uint4 u) {
    float2 p0 = __half22float2(*(__half2*)&u.x);
    float2 p1 = __half22float2(*(__half2*)&u.y);
    float2 p2 = __half22float2(*(__half2*)&u.z);
    float2 p3 = __half22float2(*(__half2*)&u.w);
    a[0] += p0.x; a[1] += p0.y; a[2] += p1.x; a[3] += p1.y;
    a[4] += p2.x; a[5] += p2.y; a[6] += p3.x; a[7] += p3.y;
}
__device__ __forceinline__ uint4 pack8(const float* a, float s) {
    __half2 h0 = __floats2half2_rn(a[0] * s, a[1] * s);
    __half2 h1 = __floats2half2_rn(a[2] * s, a[3] * s);
    __half2 h2 = __floats2half2_rn(a[4] * s, a[5] * s);
    __half2 h3 = __floats2half2_rn(a[6] * s, a[7] * s);
    uint4 u;
    u.x = *(uint32_t*)&h0; u.y = *(uint32_t*)&h1;
    u.z = *(uint32_t*)&h2; u.w = *(uint32_t*)&h3;
    return u;
}
__device__ __forceinline__ uint32_t s2u(const void* p) {
    uint32_t a;
    asm("{ .reg .u64 t; cvta.to.shared.u64 t, %1; cvt.u32.u64 %0, t; }" : "=r"(a) : "l"(p));
    return a;
}
__device__ __forceinline__ void ldsm4(uint32_t* r, uint32_t addr) {
    asm volatile("ldmatrix.sync.aligned.m8n8.x4.shared.b16 {%0,%1,%2,%3}, [%4];"
                 : "=r"(r[0]), "=r"(r[1]), "=r"(r[2]), "=r"(r[3]) : "r"(addr));
}
__device__ __forceinline__ void mma16816(float* c, const uint32_t* a, const uint32_t* b) {
    asm volatile(
        "mma.sync.aligned.m16n8k16.row.col.f32.f16.f16.f32 "
        "{%0,%1,%2,%3}, {%4,%5,%6,%7}, {%8,%9}, {%0,%1,%2,%3};"
        : "+f"(c[0]), "+f"(c[1]), "+f"(c[2]), "+f"(c[3])
        : "r"(a[0]), "r"(a[1]), "r"(a[2]), "r"(a[3]), "r"(b[0]), "r"(b[1]));
}

// ---------------- degree / norm ----------------
__global__ void k_zero_cnt() {
    int i = blockIdx.x * blockDim.x + threadIdx.x;
    if (i < N_NODES) g_cnt[i] = 0;
}
__global__ void k_hist(const int* __restrict__ dst) {
    int e = blockIdx.x * blockDim.x + threadIdx.x;
    if (e < N_EDGES) atomicAdd(&g_cnt[dst[e]], 1);
}
__global__ void k_norm() {
    int i = blockIdx.x * blockDim.x + threadIdx.x;
    if (i < N_NODES) {
        int d = g_cnt[i];
        if (d < 1) d = 1;
        g_norm[i] = rsqrtf((float)d);
    }
}

// ---------------- exclusive scan ----------------
#define SCAN_T 512
#define SCAN_NB ((N_NODES + SCAN_T - 1) / SCAN_T)   // 196

__global__ void k_scan1() {
    __shared__ int sh[SCAN_T];
    int tid = threadIdx.x;
    int gi  = blockIdx.x * SCAN_T + tid;
    int v   = (gi < N_NODES) ? g_cnt[gi] : 0;
    sh[tid] = v;
    __syncthreads();
    for (int off = 1; off < SCAN_T; off <<= 1) {
        int t = (tid >= off) ? sh[tid - off] : 0;
        __syncthreads();
        sh[tid] += t;
        __syncthreads();
    }
    if (gi < N_NODES) g_row[gi] = sh[tid] - v;
    if (tid == SCAN_T - 1) g_bsum[blockIdx.x] = sh[tid];
}
__global__ void k_scan2() {
    __shared__ int sh[256];
    int t = threadIdx.x;
    int v = (t < SCAN_NB) ? g_bsum[t] : 0;
    sh[t] = v;
    __syncthreads();
    for (int off = 1; off < 256; off <<= 1) {
        int u = (t >= off) ? sh[t - off] : 0;
        __syncthreads();
        sh[t] += u;
        __syncthreads();
    }
    if (t < SCAN_NB) g_bsum[t] = sh[t] - v;
}
__global__ void k_scan3() {
    int gi = blockIdx.x * SCAN_T + threadIdx.x;
    if (gi < N_NODES) {
        int v = g_row[gi] + g_bsum[blockIdx.x];
        g_row[gi] = v;
        g_cur[gi] = v;
    }
    if (gi == 0) g_row[N_NODES] = N_EDGES;
}
__global__ void k_fill(const int* __restrict__ src, const int* __restrict__ dst) {
    int e = blockIdx.x * blockDim.x + threadIdx.x;
    if (e < N_EDGES) {
        int d   = dst[e];
        int pos = atomicAdd(&g_cur[d], 1);
        g_csr_src[pos] = src[e];
    }
}

// ---------------- W prep: transpose + fp16 hi/lo split ----------------
__global__ void k_prepW(const float* __restrict__ W1, const float* __restrict__ W2) {
    int idx = blockIdx.x * blockDim.x + threadIdx.x;   // 512*128
    if (idx >= 512 * 128) return;
    int k = idx >> 7;
    int n = idx & 127;
    float w1 = W1[idx];
    __half h1 = __float2half_rn(w1);
    g_Wh1[n * 512 + k] = h1;
    g_Wl1[n * 512 + k] = __float2half_rn(w1 - __half2float(h1));
    float w2 = W2[idx];
    __half h2 = __float2half_rn(w2);
    g_Wh2[n * 512 + k] = h2;
    g_Wl2[n * 512 + k] = __float2half_rn(w2 - __half2float(h2));
}

// ---------------- copy x -> msg0 = x * nm (fp16) ----------------
__global__ void k_copy0(const float4* __restrict__ x4) {
    int idx = blockIdx.x * blockDim.x + threadIdx.x;   // N*16
    int node = idx >> 4;
    int q    = idx & 15;
    float4 v0 = x4[node * 32 + q * 2];
    float4 v1 = x4[node * 32 + q * 2 + 1];
    float a[8] = {v0.x, v0.y, v0.z, v0.w, v1.x, v1.y, v1.z, v1.w};
    g_msg0[(size_t)node * 16 + q] = pack8(a, g_norm[node]);
}

// ---------------- aggregation: half-warp per node, uint4 gathers, unroll 8 ----------------
// out[m] = (sum_{e in row m} in[src]) * nm[m]^2       (= feats * nm, msg invariant)
__global__ __launch_bounds__(256) void k_agg(const uint4* __restrict__ tin,
                                             uint4* __restrict__ tout) {
    int hw   = threadIdx.x >> 4;                       // 0..15
    int hl   = threadIdx.x & 15;
    int node = blockIdx.x * 16 + hw;                   // grid = 6250, exact

    int beg = g_row[node];
    int end = g_row[node + 1];

    float acc[8] = {0.f, 0.f, 0.f, 0.f, 0.f, 0.f, 0.f, 0.f};
    int e = beg;
    for (; e + 8 <= end; e += 8) {
        int s0 = __ldg(&g_csr_src[e + 0]);
        int s1 = __ldg(&g_csr_src[e + 1]);
        int s2 = __ldg(&g_csr_src[e + 2]);
        int s3 = __ldg(&g_csr_src[e + 3]);
        int s4 = __ldg(&g_csr_src[e + 4]);
        int s5 = __ldg(&g_csr_src[e + 5]);
        int s6 = __ldg(&g_csr_src[e + 6]);
        int s7 = __ldg(&g_csr_src[e + 7]);
        uint4 u0 = tin[(size_t)s0 * 16 + hl];
        uint4 u1 = tin[(size_t)s1 * 16 + hl];
        uint4 u2 = tin[(size_t)s2 * 16 + hl];
        uint4 u3 = tin[(size_t)s3 * 16 + hl];
        uint4 u4 = tin[(size_t)s4 * 16 + hl];
        uint4 u5 = tin[(size_t)s5 * 16 + hl];
        uint4 u6 = tin[(size_t)s6 * 16 + hl];
        uint4 u7 = tin[(size_t)s7 * 16 + hl];
        add8(acc, u0); add8(acc, u1); add8(acc, u2); add8(acc, u3);
        add8(acc, u4); add8(acc, u5); add8(acc, u6); add8(acc, u7);
    }
    for (; e < end; e++) {
        int s = __ldg(&g_csr_src[e]);
        add8(acc, tin[(size_t)s * 16 + hl]);
    }

    float nm = g_norm[node];
    tout[(size_t)node * 16 + hl] = pack8(acc, nm * nm);
}

// ---------------- HMMA GEMM: relu((msgcat[M,512] @ W) / nm + b) ----------------
// Block tile 128x128, 256 threads = 4(M) x 2(N) warps, each warp 32x64.
#define ASTRIDE 80
__global__ __launch_bounds__(256) void k_gemm_mma(const __half* __restrict__ m0,
                                                  const __half* __restrict__ m1,
                                                  const __half* __restrict__ m2,
                                                  const __half* __restrict__ m3,
                                                  const __half* __restrict__ Wh,
                                                  const __half* __restrict__ Wl,
                                                  const float* __restrict__ bias,
                                                  float* __restrict__ out,
                                                  int mode) {
    __shared__ __align__(16) char sA [128 * ASTRIDE];
    __shared__ __align__(16) char sBh[128 * ASTRIDE];
    __shared__ __align__(16) char sBl[128 * ASTRIDE];
    __shared__ float sBias[128];

    int tid  = threadIdx.x;
    int lane = tid & 31;
    int wid  = tid >> 5;
    int wm   = wid & 3;          // M offset wm*32
    int wn   = wid >> 2;         // N offset wn*64
    int row0 = blockIdx.x * 128;

    if (tid < 128) sBias[tid] = bias[tid];

    uint32_t aA = s2u(sA), aBh = s2u(sBh), aBl = s2u(sBl);

    uint32_t aRow = (lane & 7) + ((lane >> 3) & 1) * 8;
    uint32_t aCol = (lane >> 4) * 16;
    uint32_t bRow = (lane & 7) + (lane >> 4) * 8;
    uint32_t bCol = ((lane >> 3) & 1) * 16;

    float acc[2][8][4];
#pragma unroll
    for (int mt = 0; mt < 2; mt++)
#pragma unroll
        for (int nt = 0; nt < 8; nt++)
#pragma unroll
            for (int q = 0; q < 4; q++) acc[mt][nt][q] = 0.f;

    // A-row staging info: each thread stages 2 uint4 per chunk
    int fr0 = tid >> 2,        fq0 = tid & 3;          // uint4 0..255
    int fr1 = (tid + 256) >> 2, fq1 = (tid + 256) & 3; // uint4 256..511
    int grow0 = row0 + fr0; if (grow0 > N_NODES - 1) grow0 = N_NODES - 1;
    int grow1 = row0 + fr1; if (grow1 > N_NODES - 1) grow1 = N_NODES - 1;

    for (int kc = 0; kc < 16; kc++) {
        // slot buffer for this k-chunk (concat layout: 4 slots x 128 halfs)
        const __half* M = (kc < 8) ? ((kc < 4) ? m0 : m1) : ((kc < 12) ? m2 : m3);
        int ko = (kc & 3) * 32;                        // half offset within slot row
        // --- stage A: 128 rows x 32 halfs ---
        {
            uint4 v0 = *((const uint4*)(M + (size_t)grow0 * FDIM + ko) + fq0);
            uint4 v1 = *((const uint4*)(M + (size_t)grow1 * FDIM + ko) + fq1);
            *(uint4*)(sA + fr0 * ASTRIDE + fq0 * 16) = v0;
            *(uint4*)(sA + fr1 * ASTRIDE + fq1 * 16) = v1;
        }
        // --- stage B: Wt[n][k] fp16 hi/lo ---
#pragma unroll
        for (int jj = 0; jj < 2; jj++) {
            int f = jj * 256 + tid;
            int r = f >> 2;
            int s = f & 3;
            size_t go = ((size_t)r * 512 + kc * 32) * 2 + s * 16;
            *(uint4*)(sBh + r * ASTRIDE + s * 16) = *(const uint4*)((const char*)Wh + go);
            *(uint4*)(sBl + r * ASTRIDE + s * 16) = *(const uint4*)((const char*)Wl + go);
        }
        __syncthreads();

#pragma unroll
        for (int ks = 0; ks < 2; ks++) {
            uint32_t kb = ks * 32;
            uint32_t ah[2][4];
#pragma unroll
            for (int mt = 0; mt < 2; mt++) {
                uint32_t row = wm * 32 + mt * 16 + aRow;
                ldsm4(ah[mt], aA + row * ASTRIDE + kb + aCol);
            }
            uint32_t bh[4][4], bl[4][4];
#pragma unroll
            for (int np = 0; np < 4; np++) {
                uint32_t row = wn * 64 + np * 16 + bRow;
                ldsm4(bh[np], aBh + row * ASTRIDE + kb + bCol);
                ldsm4(bl[np], aBl + row * ASTRIDE + kb + bCol);
            }
#pragma unroll
            for (int mt = 0; mt < 2; mt++)
#pragma unroll
                for (int nt = 0; nt < 8; nt++) {
                    const uint32_t* fh = &bh[nt >> 1][(nt & 1) * 2];
                    const uint32_t* fl = &bl[nt >> 1][(nt & 1) * 2];
                    float* c = acc[mt][nt];
                    mma16816(c, ah[mt], fh);   // A*Whi
                    mma16816(c, ah[mt], fl);   // A*Wlo
                }
        }
        __syncthreads();
    }

    // --- epilogue: unscale by 1/nm, bias, relu, fused stores ---
    int qr = lane >> 2;
    int qc = lane & 3;
#pragma unroll
    for (int mt = 0; mt < 2; mt++) {
#pragma unroll
        for (int half = 0; half < 2; half++) {
            int m = row0 + wm * 32 + mt * 16 + qr + half * 8;
            if (m >= N_NODES) continue;
            float nm  = g_norm[m];
            float rnm = 1.0f / nm;
            uint32_t* mrow = (uint32_t*)g_msg0 + (size_t)m * 64;     // 128 halfs
            float*    orow = out + (size_t)m * FDIM;
#pragma unroll
            for (int nt = 0; nt < 8; nt++) {
                int col = wn * 64 + nt * 8 + qc * 2;
                float c0 = acc[mt][nt][half * 2 + 0] * rnm + sBias[col];
                float c1 = acc[mt][nt][half * 2 + 1] * rnm + sBias[col + 1];
                c0 = c0 > 0.f ? c0 : 0.f;
                c1 = c1 > 0.f ? c1 : 0.f;
                if (mode == 1) {
                    __half2 t = __floats2half2_rn(c0 * nm, c1 * nm);
                    mrow[col >> 1] = *(uint32_t*)&t;   // msg0 for layer 2
                } else {
                    *(float2*)(orow + col) = make_float2(c0, c1);
                }
            }
        }
    }
}

// ---------------- launch ----------------
extern "C" void kernel_launch(void* const* d_in, const int* in_sizes, int n_in,
                              void* d_out, int out_size) {
    const float* x  = (const float*)d_in[0];
    const int*   ei = (const int*)  d_in[1];
    const float* W1 = (const float*)d_in[2];
    const float* b1 = (const float*)d_in[3];
    const float* W2 = (const float*)d_in[4];
    const float* b2 = (const float*)d_in[5];
    float* out = (float*)d_out;

    const int* src = ei;
    const int* dst = ei + N_EDGES;

    const int TB = 256;
    const int gN = (N_NODES + TB - 1) / TB;
    const int gE = (N_EDGES + TB - 1) / TB;

    __half *wh1, *wl1, *wh2, *wl2;
    uint4 *p0, *p1, *p2, *p3;
    cudaGetSymbolAddress((void**)&wh1, g_Wh1);
    cudaGetSymbolAddress((void**)&wl1, g_Wl1);
    cudaGetSymbolAddress((void**)&wh2, g_Wh2);
    cudaGetSymbolAddress((void**)&wl2, g_Wl2);
    cudaGetSymbolAddress((void**)&p0, g_msg0);
    cudaGetSymbolAddress((void**)&p1, g_msg1);
    cudaGetSymbolAddress((void**)&p2, g_msg2);
    cudaGetSymbolAddress((void**)&p3, g_msg3);

    // --- CSR-by-dst build + norms + W prep ---
    k_zero_cnt<<<gN, TB>>>();
    k_hist<<<gE, TB>>>(dst);
    k_norm<<<gN, TB>>>();
    k_scan1<<<SCAN_NB, SCAN_T>>>();
    k_scan2<<<1, 256>>>();
    k_scan3<<<SCAN_NB, SCAN_T>>>();
    k_fill<<<gE, TB>>>(src, dst);
    k_prepW<<<(512 * 128) / TB, TB>>>(W1, W2);

    const int gAgg  = N_NODES / 16;                     // 6250
    const int gCpy  = (N_NODES * 16) / TB;              // 6250
    const int gGemm = (N_NODES + 127) / 128;            // 782

    // --- layer 1 ---
    k_copy0<<<gCpy, TB>>>((const float4*)x);
    k_agg<<<gAgg, TB>>>(p0, p1);
    k_agg<<<gAgg, TB>>>(p1, p2);
    k_agg<<<gAgg, TB>>>(p2, p3);
    k_gemm_mma<<<gGemm, TB>>>((const __half*)p0, (const __half*)p1, (const __half*)p2,
                              (const __half*)p3, wh1, wl1, b1, nullptr, 1);

    // --- layer 2 ---
    k_agg<<<gAgg, TB>>>(p0, p1);
    k_agg<<<gAgg, TB>>>(p1, p2);
    k_agg<<<gAgg, TB>>>(p2, p3);
    k_gemm_mma<<<gGemm, TB>>>((const __half*)p0, (const __half*)p1, (const __half*)p2,
                              (const __half*)p3, wh2, wl2, b2, out, 2);
}

// round 9
// speedup vs baseline: 2.3284x; 1.0402x over previous
#include <cuda_runtime.h>
#include <cuda_fp16.h>
#include <cstdint>

#define N_NODES 100000
#define N_EDGES 1600000
#define FDIM    128
#define CONCAT  512            // (K+1)*128

// ---------------- static scratch (allocation-free) ----------------
__device__ int     g_cnt[N_NODES];
__device__ int     g_row[N_NODES + 1];
__device__ int     g_cur[N_NODES];
__device__ int     g_bsum[256];                      // 196 used
__device__ int     g_csr_src[N_EDGES];
__device__ float   g_norm[N_NODES];
// fp16 message buffers, one per hop slot: [N][128] halfs = 16 uint4 per node
// invariant: msg_s[m] = feats_s[m] * nm[m]  (so feats = msg / nm, row-uniform)
__device__ uint4   g_msg0[(size_t)N_NODES * 16];
__device__ uint4   g_msg1[(size_t)N_NODES * 16];
__device__ uint4   g_msg2[(size_t)N_NODES * 16];
__device__ uint4   g_msg3[(size_t)N_NODES * 16];
// W transposed to [n][k], fp16 hi/lo split
__device__ __half  g_Wh1[128 * 512];
__device__ __half  g_Wl1[128 * 512];
__device__ __half  g_Wh2[128 * 512];
__device__ __half  g_Wl2[128 * 512];

__device__ __forceinline__ void add8(float* a, uint4 u) {
    float2 p0 = __half22float2(*(__half2*)&u.x);
    float2 p1 = __half22float2(*(__half2*)&u.y);
    float2 p2 = __half22float2(*(__half2*)&u.z);
    float2 p3 = __half22float2(*(__half2*)&u.w);
    a[0] += p0.x; a[1] += p0.y; a[2] += p1.x; a[3] += p1.y;
    a[4] += p2.x; a[5] += p2.y; a[6] += p3.x; a[7] += p3.y;
}
// fp16 pairwise add of 8 halfs
__device__ __forceinline__ uint4 h2add8(uint4 a, uint4 b) {
    uint4 r;
    *(__half2*)&r.x = __hadd2(*(__half2*)&a.x, *(__half2*)&b.x);
    *(__half2*)&r.y = __hadd2(*(__half2*)&a.y, *(__half2*)&b.y);
    *(__half2*)&r.z = __hadd2(*(__half2*)&a.z, *(__half2*)&b.z);
    *(__half2*)&r.w = __hadd2(*(__half2*)&a.w, *(__half2*)&b.w);
    return r;
}
__device__ __forceinline__ uint4 pack8(const float* a, float s) {
    __half2 h0 = __floats2half2_rn(a[0] * s, a[1] * s);
    __half2 h1 = __floats2half2_rn(a[2] * s, a[3] * s);
    __half2 h2 = __floats2half2_rn(a[4] * s, a[5] * s);
    __half2 h3 = __floats2half2_rn(a[6] * s, a[7] * s);
    uint4 u;
    u.x = *(uint32_t*)&h0; u.y = *(uint32_t*)&h1;
    u.z = *(uint32_t*)&h2; u.w = *(uint32_t*)&h3;
    return u;
}
__device__ __forceinline__ uint32_t s2u(const void* p) {
    uint32_t a;
    asm("{ .reg .u64 t; cvta.to.shared.u64 t, %1; cvt.u32.u64 %0, t; }" : "=r"(a) : "l"(p));
    return a;
}
__device__ __forceinline__ void ldsm4(uint32_t* r, uint32_t addr) {
    asm volatile("ldmatrix.sync.aligned.m8n8.x4.shared.b16 {%0,%1,%2,%3}, [%4];"
                 : "=r"(r[0]), "=r"(r[1]), "=r"(r[2]), "=r"(r[3]) : "r"(addr));
}
__device__ __forceinline__ void mma16816(float* c, const uint32_t* a, const uint32_t* b) {
    asm volatile(
        "mma.sync.aligned.m16n8k16.row.col.f32.f16.f16.f32 "
        "{%0,%1,%2,%3}, {%4,%5,%6,%7}, {%8,%9}, {%0,%1,%2,%3};"
        : "+f"(c[0]), "+f"(c[1]), "+f"(c[2]), "+f"(c[3])
        : "r"(a[0]), "r"(a[1]), "r"(a[2]), "r"(a[3]), "r"(b[0]), "r"(b[1]));
}

// ---------------- CSR build ----------------
__global__ void k_hist(const int* __restrict__ dst) {
    int e = blockIdx.x * blockDim.x + threadIdx.x;
    if (e < N_EDGES) atomicAdd(&g_cnt[dst[e]], 1);
}

#define SCAN_T 512
#define SCAN_NB ((N_NODES + SCAN_T - 1) / SCAN_T)   // 196

// scan1: per-block exclusive scan of degrees; also computes g_norm
__global__ void k_scan1() {
    __shared__ int sh[SCAN_T];
    int tid = threadIdx.x;
    int gi  = blockIdx.x * SCAN_T + tid;
    int v   = (gi < N_NODES) ? g_cnt[gi] : 0;
    if (gi < N_NODES) {
        int d = v < 1 ? 1 : v;
        g_norm[gi] = rsqrtf((float)d);
    }
    sh[tid] = v;
    __syncthreads();
    for (int off = 1; off < SCAN_T; off <<= 1) {
        int t = (tid >= off) ? sh[tid - off] : 0;
        __syncthreads();
        sh[tid] += t;
        __syncthreads();
    }
    if (gi < N_NODES) g_row[gi] = sh[tid] - v;
    if (tid == SCAN_T - 1) g_bsum[blockIdx.x] = sh[tid];
}

// scan3: add block-prefix (computed in-block from g_bsum) and init g_cur
__global__ void k_scan3() {
    __shared__ int s_off;
    int tid = threadIdx.x;
    int bid = blockIdx.x;
    if (tid < 32) {
        int s = 0;
        for (int i = tid; i < bid; i += 32) s += g_bsum[i];
#pragma unroll
        for (int o = 16; o > 0; o >>= 1) s += __shfl_down_sync(0xFFFFFFFF, s, o);
        if (tid == 0) s_off = s;
    }
    __syncthreads();
    int gi = bid * SCAN_T + tid;
    if (gi < N_NODES) {
        int v = g_row[gi] + s_off;
        g_row[gi] = v;
        g_cur[gi] = v;
    }
    if (gi == 0) g_row[N_NODES] = N_EDGES;
}

__global__ void k_fill(const int* __restrict__ src, const int* __restrict__ dst) {
    int e = blockIdx.x * blockDim.x + threadIdx.x;
    if (e < N_EDGES) {
        int d   = dst[e];
        int pos = atomicAdd(&g_cur[d], 1);
        g_csr_src[pos] = src[e];
    }
}

// ---------------- W prep: transpose + fp16 hi/lo split ----------------
__global__ void k_prepW(const float* __restrict__ W1, const float* __restrict__ W2) {
    int idx = blockIdx.x * blockDim.x + threadIdx.x;   // 512*128
    if (idx >= 512 * 128) return;
    int k = idx >> 7;
    int n = idx & 127;
    float w1 = W1[idx];
    __half h1 = __float2half_rn(w1);
    g_Wh1[n * 512 + k] = h1;
    g_Wl1[n * 512 + k] = __float2half_rn(w1 - __half2float(h1));
    float w2 = W2[idx];
    __half h2 = __float2half_rn(w2);
    g_Wh2[n * 512 + k] = h2;
    g_Wl2[n * 512 + k] = __float2half_rn(w2 - __half2float(h2));
}

// ---------------- copy x -> msg0 = x * nm (fp16) ----------------
__global__ void k_copy0(const float4* __restrict__ x4) {
    int idx = blockIdx.x * blockDim.x + threadIdx.x;   // N*16
    int node = idx >> 4;
    int q    = idx & 15;
    float4 v0 = x4[node * 32 + q * 2];
    float4 v1 = x4[node * 32 + q * 2 + 1];
    float a[8] = {v0.x, v0.y, v0.z, v0.w, v1.x, v1.y, v1.z, v1.w};
    g_msg0[(size_t)node * 16 + q] = pack8(a, g_norm[node]);
}

// ---------------- aggregation: half-warp per node, fp16 quad-tree sums ----------------
// out[m] = (sum_{e in row m} in[src]) * nm[m]^2
__global__ __launch_bounds__(256) void k_agg(const uint4* __restrict__ tin,
                                             uint4* __restrict__ tout) {
    int hw   = threadIdx.x >> 4;                       // 0..15
    int hl   = threadIdx.x & 15;
    int node = blockIdx.x * 16 + hw;                   // grid = 6250, exact

    int beg = g_row[node];
    int end = g_row[node + 1];

    float acc[8] = {0.f, 0.f, 0.f, 0.f, 0.f, 0.f, 0.f, 0.f};

    // head: advance to 4-aligned edge index
    int e = beg;
    int alignEnd = (beg + 3) & ~3;
    if (alignEnd > end) alignEnd = end;
    for (; e < alignEnd; e++) {
        int s = __ldg(&g_csr_src[e]);
        add8(acc, tin[(size_t)s * 16 + hl]);
    }
    // main: 4 edges per iter, vector index load + fp16 quad tree
    for (; e + 4 <= end; e += 4) {
        int4 s4 = *(const int4*)&g_csr_src[e];         // 16B aligned
        uint4 u0 = tin[(size_t)s4.x * 16 + hl];
        uint4 u1 = tin[(size_t)s4.y * 16 + hl];
        uint4 u2 = tin[(size_t)s4.z * 16 + hl];
        uint4 u3 = tin[(size_t)s4.w * 16 + hl];
        uint4 q = h2add8(h2add8(u0, u1), h2add8(u2, u3));
        add8(acc, q);
    }
    // tail
    for (; e < end; e++) {
        int s = __ldg(&g_csr_src[e]);
        add8(acc, tin[(size_t)s * 16 + hl]);
    }

    float nm = g_norm[node];
    tout[(size_t)node * 16 + hl] = pack8(acc, nm * nm);
}

// ---------------- HMMA GEMM: relu((msgcat[M,512] @ W) / nm + b) ----------------
// Block tile 128x128, 256 threads = 4(M) x 2(N) warps, each warp 32x64.
#define ASTRIDE 80
__global__ __launch_bounds__(256) void k_gemm_mma(const __half* __restrict__ m0,
                                                  const __half* __restrict__ m1,
                                                  const __half* __restrict__ m2,
                                                  const __half* __restrict__ m3,
                                                  const __half* __restrict__ Wh,
                                                  const __half* __restrict__ Wl,
                                                  const float* __restrict__ bias,
                                                  float* __restrict__ out,
                                                  int mode) {
    __shared__ __align__(16) char sA [128 * ASTRIDE];
    __shared__ __align__(16) char sBh[128 * ASTRIDE];
    __shared__ __align__(16) char sBl[128 * ASTRIDE];
    __shared__ float sBias[128];

    int tid  = threadIdx.x;
    int lane = tid & 31;
    int wid  = tid >> 5;
    int wm   = wid & 3;          // M offset wm*32
    int wn   = wid >> 2;         // N offset wn*64
    int row0 = blockIdx.x * 128;

    if (tid < 128) sBias[tid] = bias[tid];

    uint32_t aA = s2u(sA), aBh = s2u(sBh), aBl = s2u(sBl);

    uint32_t aRow = (lane & 7) + ((lane >> 3) & 1) * 8;
    uint32_t aCol = (lane >> 4) * 16;
    uint32_t bRow = (lane & 7) + (lane >> 4) * 8;
    uint32_t bCol = ((lane >> 3) & 1) * 16;

    float acc[2][8][4];
#pragma unroll
    for (int mt = 0; mt < 2; mt++)
#pragma unroll
        for (int nt = 0; nt < 8; nt++)
#pragma unroll
            for (int q = 0; q < 4; q++) acc[mt][nt][q] = 0.f;

    int fr0 = tid >> 2,         fq0 = tid & 3;
    int fr1 = (tid + 256) >> 2, fq1 = (tid + 256) & 3;
    int grow0 = row0 + fr0; if (grow0 > N_NODES - 1) grow0 = N_NODES - 1;
    int grow1 = row0 + fr1; if (grow1 > N_NODES - 1) grow1 = N_NODES - 1;

    for (int kc = 0; kc < 16; kc++) {
        const __half* M = (kc < 8) ? ((kc < 4) ? m0 : m1) : ((kc < 12) ? m2 : m3);
        int ko = (kc & 3) * 32;
        {
            uint4 v0 = *((const uint4*)(M + (size_t)grow0 * FDIM + ko) + fq0);
            uint4 v1 = *((const uint4*)(M + (size_t)grow1 * FDIM + ko) + fq1);
            *(uint4*)(sA + fr0 * ASTRIDE + fq0 * 16) = v0;
            *(uint4*)(sA + fr1 * ASTRIDE + fq1 * 16) = v1;
        }
#pragma unroll
        for (int jj = 0; jj < 2; jj++) {
            int f = jj * 256 + tid;
            int r = f >> 2;
            int s = f & 3;
            size_t go = ((size_t)r * 512 + kc * 32) * 2 + s * 16;
            *(uint4*)(sBh + r * ASTRIDE + s * 16) = *(const uint4*)((const char*)Wh + go);
            *(uint4*)(sBl + r * ASTRIDE + s * 16) = *(const uint4*)((const char*)Wl + go);
        }
        __syncthreads();

#pragma unroll
        for (int ks = 0; ks < 2; ks++) {
            uint32_t kb = ks * 32;
            uint32_t ah[2][4];
#pragma unroll
            for (int mt = 0; mt < 2; mt++) {
                uint32_t row = wm * 32 + mt * 16 + aRow;
                ldsm4(ah[mt], aA + row * ASTRIDE + kb + aCol);
            }
            uint32_t bh[4][4], bl[4][4];
#pragma unroll
            for (int np = 0; np < 4; np++) {
                uint32_t row = wn * 64 + np * 16 + bRow;
                ldsm4(bh[np], aBh + row * ASTRIDE + kb + bCol);
                ldsm4(bl[np], aBl + row * ASTRIDE + kb + bCol);
            }
#pragma unroll
            for (int mt = 0; mt < 2; mt++)
#pragma unroll
                for (int nt = 0; nt < 8; nt++) {
                    const uint32_t* fh = &bh[nt >> 1][(nt & 1) * 2];
                    const uint32_t* fl = &bl[nt >> 1][(nt & 1) * 2];
                    float* c = acc[mt][nt];
                    mma16816(c, ah[mt], fh);   // A*Whi
                    mma16816(c, ah[mt], fl);   // A*Wlo
                }
        }
        __syncthreads();
    }

    // --- epilogue: unscale by 1/nm, bias, relu, fused stores ---
    int qr = lane >> 2;
    int qc = lane & 3;
#pragma unroll
    for (int mt = 0; mt < 2; mt++) {
#pragma unroll
        for (int half = 0; half < 2; half++) {
            int m = row0 + wm * 32 + mt * 16 + qr + half * 8;
            if (m >= N_NODES) continue;
            float nm  = g_norm[m];
            float rnm = 1.0f / nm;
            uint32_t* mrow = (uint32_t*)g_msg0 + (size_t)m * 64;
            float*    orow = out + (size_t)m * FDIM;
#pragma unroll
            for (int nt = 0; nt < 8; nt++) {
                int col = wn * 64 + nt * 8 + qc * 2;
                float c0 = acc[mt][nt][half * 2 + 0] * rnm + sBias[col];
                float c1 = acc[mt][nt][half * 2 + 1] * rnm + sBias[col + 1];
                c0 = c0 > 0.f ? c0 : 0.f;
                c1 = c1 > 0.f ? c1 : 0.f;
                if (mode == 1) {
                    __half2 t = __floats2half2_rn(c0 * nm, c1 * nm);
                    mrow[col >> 1] = *(uint32_t*)&t;   // msg0 for layer 2
                } else {
                    *(float2*)(orow + col) = make_float2(c0, c1);
                }
            }
        }
    }
}

// ---------------- launch ----------------
extern "C" void kernel_launch(void* const* d_in, const int* in_sizes, int n_in,
                              void* d_out, int out_size) {
    const float* x  = (const float*)d_in[0];
    const int*   ei = (const int*)  d_in[1];
    const float* W1 = (const float*)d_in[2];
    const float* b1 = (const float*)d_in[3];
    const float* W2 = (const float*)d_in[4];
    const float* b2 = (const float*)d_in[5];
    float* out = (float*)d_out;

    const int* src = ei;
    const int* dst = ei + N_EDGES;

    const int TB = 256;
    const int gE = (N_EDGES + TB - 1) / TB;

    __half *wh1, *wl1, *wh2, *wl2;
    uint4 *p0, *p1, *p2, *p3;
    int* cnt;
    cudaGetSymbolAddress((void**)&wh1, g_Wh1);
    cudaGetSymbolAddress((void**)&wl1, g_Wl1);
    cudaGetSymbolAddress((void**)&wh2, g_Wh2);
    cudaGetSymbolAddress((void**)&wl2, g_Wl2);
    cudaGetSymbolAddress((void**)&p0, g_msg0);
    cudaGetSymbolAddress((void**)&p1, g_msg1);
    cudaGetSymbolAddress((void**)&p2, g_msg2);
    cudaGetSymbolAddress((void**)&p3, g_msg3);
    cudaGetSymbolAddress((void**)&cnt, g_cnt);

    // --- CSR-by-dst build + norms + W prep ---
    cudaMemsetAsync(cnt, 0, N_NODES * sizeof(int));
    k_hist<<<gE, TB>>>(dst);
    k_scan1<<<SCAN_NB, SCAN_T>>>();       // also computes g_norm
    k_scan3<<<SCAN_NB, SCAN_T>>>();       // block-prefix computed in-block
    k_fill<<<gE, TB>>>(src, dst);
    k_prepW<<<(512 * 128) / TB, TB>>>(W1, W2);

    const int gAgg  = N_NODES / 16;                     // 6250
    const int gCpy  = (N_NODES * 16) / TB;              // 6250
    const int gGemm = (N_NODES + 127) / 128;            // 782

    // --- layer 1 ---
    k_copy0<<<gCpy, TB>>>((const float4*)x);
    k_agg<<<gAgg, TB>>>(p0, p1);
    k_agg<<<gAgg, TB>>>(p1, p2);
    k_agg<<<gAgg, TB>>>(p2, p3);
    k_gemm_mma<<<gGemm, TB>>>((const __half*)p0, (const __half*)p1, (const __half*)p2,
                              (const __half*)p3, wh1, wl1, b1, nullptr, 1);

    // --- layer 2 ---
    k_agg<<<gAgg, TB>>>(p0, p1);
    k_agg<<<gAgg, TB>>>(p1, p2);
    k_agg<<<gAgg, TB>>>(p2, p3);
    k_gemm_mma<<<gGemm, TB>>>((const __half*)p0, (const __half*)p1, (const __half*)p2,
                              (const __half*)p3, wh2, wl2, b2, out, 2);
}